// round 14
// baseline (speedup 1.0000x reference)
#include <cuda_runtime.h>
#include <cuda_bf16.h>

// embeddings [B=512, I=128, D=64] fp32
// out[b,i,d] = tanh( emb[b,i,d] * (1/I) * sum_j emb[b,j,d] )
//
// R14: all R2 invariants (4 full 128B lines per warp-LDG, 4xfloat4
// reg-resident buffer in a 32-reg budget, single wave, cheap reduce)
// at MAXIMUM occupancy: 512 CTAs x 512 threads = up to 2048 thr/SM
// (100% of capacity, vs R2's 87.5%). One CTA per batch, full 16-f4-col
// rows. Thread t: c=t&15, rg=t>>4, rows rg+32k. Warp reduce is a single
// shfl_xor(16); 16x16 smem stage; 16-thread final; tanh; 4 STG.128.

static constexpr int BATCH   = 512;
static constexpr int SEQ_I   = 128;
static constexpr int F4_ROW  = 16;      // 64 floats / 4
static constexpr int THREADS = 512;

__device__ __forceinline__ float fast_tanh(float x) {
    float y;
    asm("tanh.approx.f32 %0, %1;" : "=f"(y) : "f"(x));
    return y;
}

__global__ __launch_bounds__(THREADS, 4)
void ATT0_40707700032104_kernel(const float4* __restrict__ in,
                                float4* __restrict__ out) {
    const int b    = blockIdx.x;
    const int t    = threadIdx.x;
    const int c    = t & (F4_ROW - 1);    // f4 column (0..15)
    const int rg   = t >> 4;              // base row (0..31)
    const int lane = t & 31;
    const int w    = t >> 5;              // warp id (0..15)

    const size_t base = (size_t)b * (SEQ_I * F4_ROW) + c;
    const float4* src = in  + base;
    float4*       dst = out + base;

    // ---- 4 independent coalesced LDG.128 (rows rg + 32k), kept in regs ----
    float4 v[4];
#pragma unroll
    for (int k = 0; k < 4; k++)
        v[k] = src[(size_t)(rg + 32 * k) * F4_ROW];

    float4 s;
    s.x = (v[0].x + v[1].x) + (v[2].x + v[3].x);
    s.y = (v[0].y + v[1].y) + (v[2].y + v[3].y);
    s.z = (v[0].z + v[1].z) + (v[2].z + v[3].z);
    s.w = (v[0].w + v[1].w) + (v[2].w + v[3].w);

    // ---- Warp reduce: lanes l and l+16 share column c -> one shuffle ----
    s.x += __shfl_xor_sync(0xffffffffu, s.x, 16);
    s.y += __shfl_xor_sync(0xffffffffu, s.y, 16);
    s.z += __shfl_xor_sync(0xffffffffu, s.z, 16);
    s.w += __shfl_xor_sync(0xffffffffu, s.w, 16);

    // ---- Cross-warp reduce via 16x16 smem stage ----
    __shared__ float4 wsum[16][F4_ROW];
    __shared__ float4 mean4[F4_ROW];
    if (lane < F4_ROW) wsum[w][lane] = s;
    __syncthreads();

    if (t < F4_ROW) {
        float4 m = wsum[0][t];
#pragma unroll
        for (int ww = 1; ww < 16; ww++) {
            float4 p = wsum[ww][t];
            m.x += p.x; m.y += p.y; m.z += p.z; m.w += p.w;
        }
        const float inv = 1.0f / (float)SEQ_I;
        m.x *= inv; m.y *= inv; m.z *= inv; m.w *= inv;
        mean4[t] = m;
    }
    __syncthreads();

    const float4 m = mean4[c];

    // ---- tanh(v * mean) from registers, 4 coalesced STG.128 ----
#pragma unroll
    for (int k = 0; k < 4; k++) {
        float4 r;
        r.x = fast_tanh(v[k].x * m.x);
        r.y = fast_tanh(v[k].y * m.y);
        r.z = fast_tanh(v[k].z * m.z);
        r.w = fast_tanh(v[k].w * m.w);
        dst[(size_t)(rg + 32 * k) * F4_ROW] = r;
    }
}

extern "C" void kernel_launch(void* const* d_in, const int* in_sizes, int n_in,
                              void* d_out, int out_size) {
    const float4* in  = (const float4*)d_in[0];
    float4*       out = (float4*)d_out;
    ATT0_40707700032104_kernel<<<BATCH, THREADS>>>(in, out);
}